// round 1
// baseline (speedup 1.0000x reference)
#include <cuda_runtime.h>
#include <cuda_bf16.h>

#define N_USERS 100000
#define N_ITEMS 150000
#define NN      250000
#define NFEAT   250002
#define NNZ     4000000
#define EMB     64
#define BATCH   512

// ---------------- scratch (device globals; no runtime allocation) ------------
__device__ int   d_cnt[NN];
__device__ int   d_rowptr[NN + 1];
__device__ int   d_pos[NN];
__device__ int   d_ccol[NNZ];
__device__ float d_cval[NNZ];
__device__ float d_repA[(size_t)NN * EMB];
__device__ float d_repB[(size_t)NN * EMB];
__device__ float d_accm[(size_t)NN * EMB];
__device__ float d_U[BATCH * EMB];

// ---------------- CSR build --------------------------------------------------
__global__ void k_zero() {
    int i = blockIdx.x * blockDim.x + threadIdx.x;
    if (i < NN) d_cnt[i] = 0;
}

__global__ void k_hist(const int* __restrict__ row) {
    int i = blockIdx.x * blockDim.x + threadIdx.x;
    int stride = gridDim.x * blockDim.x;
    for (; i < NNZ; i += stride) atomicAdd(&d_cnt[row[i]], 1);
}

// single-block scan over 250K counters
__global__ void k_scan() {
    const int T = 1024;
    const int CH = (NN + T - 1) / T;   // 245
    int t = threadIdx.x;
    int start = t * CH;
    int stop  = min(start + CH, NN);
    int s = 0;
    for (int i = start; i < stop; i++) s += d_cnt[i];
    __shared__ int sh[T];
    sh[t] = s;
    __syncthreads();
    for (int off = 1; off < T; off <<= 1) {
        int v = (t >= off) ? sh[t - off] : 0;
        __syncthreads();
        sh[t] += v;
        __syncthreads();
    }
    int run = (t == 0) ? 0 : sh[t - 1];
    for (int i = start; i < stop; i++) {
        d_rowptr[i] = run;
        d_pos[i]    = run;
        run += d_cnt[i];
    }
    if (t == T - 1) d_rowptr[NN] = sh[T - 1];
}

__global__ void k_scatter(const int* __restrict__ row, const int* __restrict__ col,
                          const float* __restrict__ val) {
    int i = blockIdx.x * blockDim.x + threadIdx.x;
    int stride = gridDim.x * blockDim.x;
    for (; i < NNZ; i += stride) {
        int r = row[i];
        int p = atomicAdd(&d_pos[r], 1);
        d_ccol[p] = col[i];
        d_cval[p] = val[i];
    }
}

// ---------------- feat SpMM (layer 0) : rep0 = fval(n)*(sum emb[nbr] + emb[self])*w
__global__ void k_rep0(const float* __restrict__ emb, const float* __restrict__ w) {
    int gw = (blockIdx.x * blockDim.x + threadIdx.x) >> 5;
    if (gw >= NN) return;
    int lane = threadIdx.x & 31;
    int beg = d_rowptr[gw], end = d_rowptr[gw + 1];
    int self = NN + (gw >= N_USERS ? 1 : 0);
    const float2* e2 = (const float2*)emb;
    float2 s = e2[(size_t)self * 32 + lane];
    for (int j0 = beg; j0 < end; j0 += 32) {
        int jj = j0 + lane;
        int c = (jj < end) ? d_ccol[jj] : 0;
        int cnt = min(32, end - j0);
        #pragma unroll 4
        for (int k = 0; k < cnt; k++) {
            int cc = __shfl_sync(0xffffffffu, c, k);
            float2 x = e2[(size_t)cc * 32 + lane];
            s.x += x.x; s.y += x.y;
        }
    }
    float fv = rsqrtf((float)(end - beg + 1));     // rs = deg + 1
    float2 w2 = ((const float2*)w)[lane];
    s.x *= fv * w2.x;
    s.y *= fv * w2.y;
    ((float2*)d_repA)[(size_t)gw * 32 + lane] = s;
    ((float2*)d_accm)[(size_t)gw * 32 + lane] = s;
}

// ---------------- adj SpMM layer: out = A * in ; acc += out ------------------
__global__ void k_spmm(int flip) {
    const float2* in  = (const float2*)(flip ? d_repB : d_repA);
    float2*       out = (float2*)      (flip ? d_repA : d_repB);
    int gw = (blockIdx.x * blockDim.x + threadIdx.x) >> 5;
    if (gw >= NN) return;
    int lane = threadIdx.x & 31;
    int beg = d_rowptr[gw], end = d_rowptr[gw + 1];
    float2 s = make_float2(0.f, 0.f);
    for (int j0 = beg; j0 < end; j0 += 32) {
        int jj = j0 + lane;
        int c = 0; float v = 0.f;
        if (jj < end) { c = d_ccol[jj]; v = d_cval[jj]; }
        int cnt = min(32, end - j0);
        #pragma unroll 4
        for (int k = 0; k < cnt; k++) {
            int   cc = __shfl_sync(0xffffffffu, c, k);
            float vv = __shfl_sync(0xffffffffu, v, k);
            float2 x = in[(size_t)cc * 32 + lane];
            s.x += vv * x.x;
            s.y += vv * x.y;
        }
    }
    size_t idx = (size_t)gw * 32 + lane;
    out[idx] = s;
    float2* a = (float2*)d_accm;
    float2 av = a[idx];
    av.x += s.x; av.y += s.y;
    a[idx] = av;
}

// ---------------- gather users, fold the /16 ---------------------------------
__global__ void k_gatherU(const int* __restrict__ users) {
    int t = blockIdx.x * blockDim.x + threadIdx.x;
    if (t < BATCH * EMB) {
        int b = t >> 6, c = t & 63;
        d_U[t] = d_accm[(size_t)users[b] * EMB + c] * (1.0f / 16.0f);
    }
}

// ---------------- final GEMM: out[512][150000] = U(512x64) * I(150000x64)^T --
// tile: 32 users x 128 items, 256 threads, thread tile 4x4, K=64 all in smem
__global__ __launch_bounds__(256) void k_gemm(float* __restrict__ out) {
    __shared__ float Us[64][36];    // [k][user] padded
    __shared__ float Is[64][132];   // [k][item] padded
    int tid = threadIdx.x;
    int tx = tid & 31;          // item group
    int ty = tid >> 5;          // user group (0..7)
    int it0 = blockIdx.x * 128;
    int u0  = blockIdx.y * 32;

    // load U tile transposed: 32 users x 64 k
    #pragma unroll
    for (int i = 0; i < 8; i++) {
        int user = i * 4 + (tid >> 6);
        int k = tid & 63;
        Us[k][user] = d_U[(u0 + user) * EMB + k];
    }
    // load I tile transposed: 128 items x 64 k
    #pragma unroll
    for (int i = 0; i < 32; i++) {
        int item = i * 4 + (tid >> 6);
        int k = tid & 63;
        int git = it0 + item;
        Is[k][item] = (git < N_ITEMS) ? d_accm[(size_t)(N_USERS + git) * EMB + k] : 0.f;
    }
    __syncthreads();

    float acc[4][4];
    #pragma unroll
    for (int u = 0; u < 4; u++)
        #pragma unroll
        for (int v = 0; v < 4; v++) acc[u][v] = 0.f;

    #pragma unroll 16
    for (int k = 0; k < 64; k++) {
        float4 uf = *(const float4*)&Us[k][ty * 4];
        float4 vf = *(const float4*)&Is[k][tx * 4];
        float u4[4] = {uf.x, uf.y, uf.z, uf.w};
        float v4[4] = {vf.x, vf.y, vf.z, vf.w};
        #pragma unroll
        for (int u = 0; u < 4; u++)
            #pragma unroll
            for (int v = 0; v < 4; v++) acc[u][v] += u4[u] * v4[v];
    }

    int it = it0 + tx * 4;
    if (it < N_ITEMS) {
        #pragma unroll
        for (int u = 0; u < 4; u++) {
            float4 r = make_float4(acc[u][0], acc[u][1], acc[u][2], acc[u][3]);
            *(float4*)&out[(size_t)(u0 + ty * 4 + u) * N_ITEMS + it] = r;
        }
    }
}

// ---------------- launch -----------------------------------------------------
extern "C" void kernel_launch(void* const* d_in, const int* in_sizes, int n_in,
                              void* d_out, int out_size) {
    const int*   users = (const int*)  d_in[0];
    const float* emb   = (const float*)d_in[1];
    const float* w     = (const float*)d_in[2];
    const int*   arow  = (const int*)  d_in[3];
    const int*   acol  = (const int*)  d_in[4];
    const float* aval  = (const float*)d_in[5];
    float* out = (float*)d_out;

    k_zero<<<(NN + 255) / 256, 256>>>();
    k_hist<<<2048, 256>>>(arow);
    k_scan<<<1, 1024>>>();
    k_scatter<<<2048, 256>>>(arow, acol, aval);

    int blocks = (NN + 7) / 8;     // warp per row, 8 warps/block
    k_rep0<<<blocks, 256>>>(emb, w);
    k_spmm<<<blocks, 256>>>(0);    // A -> B
    k_spmm<<<blocks, 256>>>(1);    // B -> A
    k_spmm<<<blocks, 256>>>(0);    // A -> B

    k_gatherU<<<(BATCH * EMB + 255) / 256, 256>>>(users);

    dim3 g((N_ITEMS + 127) / 128, BATCH / 32);
    k_gemm<<<g, 256>>>(out);
}

// round 2
// speedup vs baseline: 2.4927x; 2.4927x over previous
#include <cuda_runtime.h>
#include <cuda_bf16.h>

#define N_USERS 100000
#define N_ITEMS 150000
#define NN      250000
#define NNZ     4000000
#define EMB     64
#define BATCH   512

#define SCAN_T  1024
#define SCAN_B  ((NN + SCAN_T - 1) / SCAN_T)   // 245

// ---------------- scratch (device globals; no runtime allocation) ------------
__device__ int   d_cnt[NN];
__device__ int   d_rowptr[NN + 1];
__device__ int   d_pos[NN];
__device__ int2  d_edge[NNZ];
__device__ int   d_bsum[SCAN_B];
__device__ int   d_boff[SCAN_B];
__device__ float d_repA[(size_t)NN * EMB];
__device__ float d_repB[(size_t)NN * EMB];
__device__ float d_accm[(size_t)NN * EMB];
__device__ float d_U[BATCH * EMB];

// ---------------- f32x2 packed-math macros (sm_103a FFMA2) -------------------
#define DUP2(d, s)    asm("mov.b64 %0, {%1, %1};" : "=l"(d) : "f"(s))
#define FMA2(acc, a, b) \
    asm("fma.rn.f32x2 %0, %1, %2, %0;" : "+l"(acc) : "l"(a), "l"(b))
#define UNPK2(lo, hi, s) \
    asm("mov.b64 {%0, %1}, %2;" : "=f"(lo), "=f"(hi) : "l"(s))

// ---------------- CSR build --------------------------------------------------
__global__ void k_zero() {
    int i = blockIdx.x * blockDim.x + threadIdx.x;
    if (i < NN) d_cnt[i] = 0;
}

__global__ void k_hist(const int* __restrict__ row) {
    int i = blockIdx.x * blockDim.x + threadIdx.x;
    int stride = gridDim.x * blockDim.x;
    for (; i < NNZ; i += stride) atomicAdd(&d_cnt[row[i]], 1);
}

// block-level inclusive scan helper (1024 threads)
__device__ __forceinline__ int block_scan_incl(int v, int tid) {
    int lane = tid & 31, w = tid >> 5;
    int x = v;
    #pragma unroll
    for (int o = 1; o < 32; o <<= 1) {
        int y = __shfl_up_sync(0xffffffffu, x, o);
        if (lane >= o) x += y;
    }
    __shared__ int ws[32];
    if (lane == 31) ws[w] = x;
    __syncthreads();
    if (w == 0) {
        int y = ws[lane];
        #pragma unroll
        for (int o = 1; o < 32; o <<= 1) {
            int z = __shfl_up_sync(0xffffffffu, y, o);
            if (lane >= o) y += z;
        }
        ws[lane] = y;
    }
    __syncthreads();
    return x + (w > 0 ? ws[w - 1] : 0);
}

__global__ void k_csr1() {   // per-block sums
    int tid = threadIdx.x;
    int i = blockIdx.x * SCAN_T + tid;
    int v = (i < NN) ? d_cnt[i] : 0;
    int incl = block_scan_incl(v, tid);
    if (tid == SCAN_T - 1) d_bsum[blockIdx.x] = incl;
}

__global__ void k_csr2() {   // 1 block of 256: scan the 245 block sums (exclusive)
    int tid = threadIdx.x;
    int v = (tid < SCAN_B) ? d_bsum[tid] : 0;
    int lane = tid & 31, w = tid >> 5;
    int x = v;
    #pragma unroll
    for (int o = 1; o < 32; o <<= 1) {
        int y = __shfl_up_sync(0xffffffffu, x, o);
        if (lane >= o) x += y;
    }
    __shared__ int ws[8];
    if (lane == 31) ws[w] = x;
    __syncthreads();
    int off = 0;
    for (int j = 0; j < w; j++) off += ws[j];
    if (tid < SCAN_B) d_boff[tid] = x + off - v;   // exclusive
}

__global__ void k_csr3() {   // final rowptr / pos
    int tid = threadIdx.x;
    int i = blockIdx.x * SCAN_T + tid;
    int v = (i < NN) ? d_cnt[i] : 0;
    int incl = block_scan_incl(v, tid);
    int excl = incl - v + d_boff[blockIdx.x];
    if (i < NN) {
        d_rowptr[i] = excl;
        d_pos[i]    = excl;
        if (i == NN - 1) d_rowptr[NN] = excl + v;
    }
}

__global__ void k_scatter(const int* __restrict__ row, const int* __restrict__ col,
                          const float* __restrict__ val) {
    int i = blockIdx.x * blockDim.x + threadIdx.x;
    int stride = gridDim.x * blockDim.x;
    for (; i < NNZ; i += stride) {
        int r = row[i];
        int p = atomicAdd(&d_pos[r], 1);
        d_edge[p] = make_int2(col[i], __float_as_int(val[i]));
    }
}

// ---------------- layer 0: rep0 = rs^-0.5 * (sum emb[nbr] + emb[self]) * w ---
// 16-lane groups, 2 rows per warp, float4 per lane
__global__ void k_rep0(const float* __restrict__ emb, const float* __restrict__ w) {
    int lane = threadIdx.x & 31;
    int l = lane & 15;
    int sbase = lane & 16;
    int gw = (blockIdx.x * blockDim.x + threadIdx.x) >> 4;
    if (gw >= NN) return;
    int beg = d_rowptr[gw], end = d_rowptr[gw + 1];
    int len = end - beg;
    int olen = __shfl_xor_sync(0xffffffffu, len, 16);
    int maxlen = max(len, olen);
    const float4* e4 = (const float4*)emb;

    int self = NN + (gw >= N_USERS ? 1 : 0);
    float4 s = e4[(size_t)self * 16 + l];

    for (int r0 = 0; r0 < maxlen; r0 += 16) {
        int jj = beg + r0 + l;
        int c = 0; float m = 0.f;
        if (jj < end) { c = d_edge[jj].x; m = 1.f; }
        int kmax = min(16, maxlen - r0);
        #pragma unroll 4
        for (int k = 0; k < kmax; k++) {
            int   cc = __shfl_sync(0xffffffffu, c, sbase + k);
            float mm = __shfl_sync(0xffffffffu, m, sbase + k);
            float4 x = e4[(size_t)cc * 16 + l];
            s.x += mm * x.x; s.y += mm * x.y; s.z += mm * x.z; s.w += mm * x.w;
        }
    }
    float fv = rsqrtf((float)(len + 1));
    float4 w4 = ((const float4*)w)[l];
    s.x *= fv * w4.x; s.y *= fv * w4.y; s.z *= fv * w4.z; s.w *= fv * w4.w;
    size_t idx = (size_t)gw * 16 + l;
    ((float4*)d_repA)[idx] = s;
    ((float4*)d_accm)[idx] = s;
}

// ---------------- adj SpMM layer: out = A * in ; acc += out ------------------
__global__ void k_spmm(int flip) {
    const float4* in  = (const float4*)(flip ? d_repB : d_repA);
    float4*       out = (float4*)      (flip ? d_repA : d_repB);
    int lane = threadIdx.x & 31;
    int l = lane & 15;
    int sbase = lane & 16;
    int gw = (blockIdx.x * blockDim.x + threadIdx.x) >> 4;
    if (gw >= NN) return;
    int beg = d_rowptr[gw], end = d_rowptr[gw + 1];
    int len = end - beg;
    int olen = __shfl_xor_sync(0xffffffffu, len, 16);
    int maxlen = max(len, olen);

    float4 s = make_float4(0.f, 0.f, 0.f, 0.f);
    for (int r0 = 0; r0 < maxlen; r0 += 16) {
        int jj = beg + r0 + l;
        int c = 0; float v = 0.f;
        if (jj < end) { int2 e = d_edge[jj]; c = e.x; v = __int_as_float(e.y); }
        int kmax = min(16, maxlen - r0);
        #pragma unroll 4
        for (int k = 0; k < kmax; k++) {
            int   cc = __shfl_sync(0xffffffffu, c, sbase + k);
            float vv = __shfl_sync(0xffffffffu, v, sbase + k);
            float4 x = in[(size_t)cc * 16 + l];
            s.x += vv * x.x; s.y += vv * x.y; s.z += vv * x.z; s.w += vv * x.w;
        }
    }
    size_t idx = (size_t)gw * 16 + l;
    out[idx] = s;
    float4* a = (float4*)d_accm;
    float4 av = a[idx];
    av.x += s.x; av.y += s.y; av.z += s.z; av.w += s.w;
    a[idx] = av;
}

// ---------------- gather users, fold the /16 ---------------------------------
__global__ void k_gatherU(const int* __restrict__ users) {
    int t = blockIdx.x * blockDim.x + threadIdx.x;
    if (t < BATCH * EMB) {
        int b = t >> 6, c = t & 63;
        d_U[t] = d_accm[(size_t)users[b] * EMB + c] * (1.0f / 16.0f);
    }
}

// ---------------- final GEMM: out[512][150000] = U(512x64) * I(150000x64)^T --
// block tile 64u x 128i, 128 threads, thread tile 8u x 8i, FFMA2 packed math
__global__ __launch_bounds__(128) void k_gemm(float* __restrict__ out) {
    __shared__ float Us[64][64];    // [k][user] 16KB
    __shared__ float Is[64][128];   // [k][item] 32KB
    int tid = threadIdx.x;
    int tx = tid & 15;              // item group (8 items)
    int ty = tid >> 4;              // user group (8 users)
    int it0 = blockIdx.x * 128;
    int u0  = blockIdx.y * 64;

    // load U tile (64 users x 64 k), transpose into Us[k][user]
    {
        int user = tid >> 1;
        int kh = (tid & 1) * 32;
        const float4* src = (const float4*)&d_U[(u0 + user) * EMB + kh];
        #pragma unroll
        for (int j = 0; j < 8; j++) {
            float4 f = src[j];
            int k = kh + j * 4;
            Us[k + 0][user] = f.x;
            Us[k + 1][user] = f.y;
            Us[k + 2][user] = f.z;
            Us[k + 3][user] = f.w;
        }
    }
    // load I tile (128 items x 64 k), transpose into Is[k][item]
    {
        int git = it0 + tid;
        if (git < N_ITEMS) {
            const float4* src = (const float4*)&d_accm[(size_t)(N_USERS + git) * EMB];
            #pragma unroll
            for (int j = 0; j < 16; j++) {
                float4 f = src[j];
                int k = j * 4;
                Is[k + 0][tid] = f.x;
                Is[k + 1][tid] = f.y;
                Is[k + 2][tid] = f.z;
                Is[k + 3][tid] = f.w;
            }
        } else {
            #pragma unroll
            for (int k = 0; k < 64; k++) Is[k][tid] = 0.f;
        }
    }
    __syncthreads();

    unsigned long long acc[8][4];
    #pragma unroll
    for (int u = 0; u < 8; u++)
        #pragma unroll
        for (int p = 0; p < 4; p++) acc[u][p] = 0ULL;

    #pragma unroll 4
    for (int k = 0; k < 64; k++) {
        float4 a0 = *(const float4*)&Us[k][ty * 8];
        float4 a1 = *(const float4*)&Us[k][ty * 8 + 4];
        const ulonglong2* ip = (const ulonglong2*)&Is[k][tx * 8];
        ulonglong2 i01 = ip[0];
        ulonglong2 i23 = ip[1];
        unsigned long long iv[4] = {i01.x, i01.y, i23.x, i23.y};
        unsigned long long ud[8];
        DUP2(ud[0], a0.x); DUP2(ud[1], a0.y); DUP2(ud[2], a0.z); DUP2(ud[3], a0.w);
        DUP2(ud[4], a1.x); DUP2(ud[5], a1.y); DUP2(ud[6], a1.z); DUP2(ud[7], a1.w);
        #pragma unroll
        for (int u = 0; u < 8; u++)
            #pragma unroll
            for (int p = 0; p < 4; p++)
                FMA2(acc[u][p], ud[u], iv[p]);
    }

    int it = it0 + tx * 8;
    bool full = (it0 + 128 <= N_ITEMS);
    #pragma unroll
    for (int u = 0; u < 8; u++) {
        float r[8];
        #pragma unroll
        for (int p = 0; p < 4; p++) UNPK2(r[2 * p], r[2 * p + 1], acc[u][p]);
        float* orow = &out[(size_t)(u0 + ty * 8 + u) * N_ITEMS + it];
        if (full) {
            *(float4*)&orow[0] = make_float4(r[0], r[1], r[2], r[3]);
            *(float4*)&orow[4] = make_float4(r[4], r[5], r[6], r[7]);
        } else {
            #pragma unroll
            for (int j = 0; j < 8; j++)
                if (it + j < N_ITEMS) orow[j] = r[j];
        }
    }
}

// ---------------- launch -----------------------------------------------------
extern "C" void kernel_launch(void* const* d_in, const int* in_sizes, int n_in,
                              void* d_out, int out_size) {
    const int*   users = (const int*)  d_in[0];
    const float* emb   = (const float*)d_in[1];
    const float* w     = (const float*)d_in[2];
    const int*   arow  = (const int*)  d_in[3];
    const int*   acol  = (const int*)  d_in[4];
    const float* aval  = (const float*)d_in[5];
    float* out = (float*)d_out;

    k_zero<<<(NN + 255) / 256, 256>>>();
    k_hist<<<2048, 256>>>(arow);
    k_csr1<<<SCAN_B, SCAN_T>>>();
    k_csr2<<<1, 256>>>();
    k_csr3<<<SCAN_B, SCAN_T>>>();
    k_scatter<<<2048, 256>>>(arow, acol, aval);

    int blocks = (NN * 16 + 255) / 256;    // 16 lanes per row
    k_rep0<<<blocks, 256>>>(emb, w);
    k_spmm<<<blocks, 256>>>(0);    // A -> B
    k_spmm<<<blocks, 256>>>(1);    // B -> A
    k_spmm<<<blocks, 256>>>(0);    // A -> B

    k_gatherU<<<(BATCH * EMB + 255) / 256, 256>>>(users);

    dim3 g((N_ITEMS + 127) / 128, BATCH / 64);
    k_gemm<<<g, 128>>>(out);
}

// round 3
// speedup vs baseline: 2.4952x; 1.0010x over previous
#include <cuda_runtime.h>
#include <cuda_bf16.h>
#include <cuda_fp16.h>

#define N_USERS 100000
#define N_ITEMS 150000
#define NN      250000
#define NFEAT   250002
#define NNZ     4000000
#define EMB     64
#define BATCH   512

#define SCAN_T  1024
#define SCAN_B  ((NN + SCAN_T - 1) / SCAN_T)   // 245

// ---------------- scratch (device globals; no runtime allocation) ------------
__device__ int    d_cnt[NN];
__device__ int    d_rowptr[NN + 1];
__device__ int    d_pos[NN];
__device__ int2   d_edge[NNZ];
__device__ int    d_bsum[SCAN_B];
__device__ int    d_boff[SCAN_B];
__device__ __half d_embH[(size_t)NFEAT * EMB];
__device__ __half d_repHA[(size_t)NN * EMB];
__device__ __half d_repHB[(size_t)NN * EMB];
__device__ float  d_accm[(size_t)NN * EMB];
__device__ float  d_U[BATCH * EMB];

// ---------------- f32x2 packed-math macros (sm_103a FFMA2) -------------------
#define DUP2(d, s)    asm("mov.b64 %0, {%1, %1};" : "=l"(d) : "f"(s))
#define FMA2(acc, a, b) \
    asm("fma.rn.f32x2 %0, %1, %2, %0;" : "+l"(acc) : "l"(a), "l"(b))
#define UNPK2(lo, hi, s) \
    asm("mov.b64 {%0, %1}, %2;" : "=f"(lo), "=f"(hi) : "l"(s))

// ---------------- emb -> fp16 ------------------------------------------------
__global__ void k_cvt_emb(const float* __restrict__ emb) {
    int i = blockIdx.x * blockDim.x + threadIdx.x;            // float4 index
    const int total = (NFEAT * EMB) / 4;
    if (i < total) {
        float4 f = ((const float4*)emb)[i];
        __half2 h0 = __floats2half2_rn(f.x, f.y);
        __half2 h1 = __floats2half2_rn(f.z, f.w);
        ((uint2*)d_embH)[i] = make_uint2(*(unsigned*)&h0, *(unsigned*)&h1);
    }
}

// ---------------- CSR build --------------------------------------------------
__global__ void k_zero() {
    int i = blockIdx.x * blockDim.x + threadIdx.x;
    if (i < NN) d_cnt[i] = 0;
}

__global__ void k_hist(const int* __restrict__ row) {
    int i = blockIdx.x * blockDim.x + threadIdx.x;
    int stride = gridDim.x * blockDim.x;
    for (; i < NNZ / 4; i += stride) {
        int4 r = ((const int4*)row)[i];
        atomicAdd(&d_cnt[r.x], 1);
        atomicAdd(&d_cnt[r.y], 1);
        atomicAdd(&d_cnt[r.z], 1);
        atomicAdd(&d_cnt[r.w], 1);
    }
}

__device__ __forceinline__ int block_scan_incl(int v, int tid) {
    int lane = tid & 31, w = tid >> 5;
    int x = v;
    #pragma unroll
    for (int o = 1; o < 32; o <<= 1) {
        int y = __shfl_up_sync(0xffffffffu, x, o);
        if (lane >= o) x += y;
    }
    __shared__ int ws[32];
    if (lane == 31) ws[w] = x;
    __syncthreads();
    if (w == 0) {
        int y = ws[lane];
        #pragma unroll
        for (int o = 1; o < 32; o <<= 1) {
            int z = __shfl_up_sync(0xffffffffu, y, o);
            if (lane >= o) y += z;
        }
        ws[lane] = y;
    }
    __syncthreads();
    return x + (w > 0 ? ws[w - 1] : 0);
}

__global__ void k_csr1() {
    int tid = threadIdx.x;
    int i = blockIdx.x * SCAN_T + tid;
    int v = (i < NN) ? d_cnt[i] : 0;
    int incl = block_scan_incl(v, tid);
    if (tid == SCAN_T - 1) d_bsum[blockIdx.x] = incl;
}

__global__ void k_csr2() {
    int tid = threadIdx.x;
    int v = (tid < SCAN_B) ? d_bsum[tid] : 0;
    int lane = tid & 31, w = tid >> 5;
    int x = v;
    #pragma unroll
    for (int o = 1; o < 32; o <<= 1) {
        int y = __shfl_up_sync(0xffffffffu, x, o);
        if (lane >= o) x += y;
    }
    __shared__ int ws[8];
    if (lane == 31) ws[w] = x;
    __syncthreads();
    int off = 0;
    for (int j = 0; j < w; j++) off += ws[j];
    if (tid < SCAN_B) d_boff[tid] = x + off - v;
}

__global__ void k_csr3() {
    int tid = threadIdx.x;
    int i = blockIdx.x * SCAN_T + tid;
    int v = (i < NN) ? d_cnt[i] : 0;
    int incl = block_scan_incl(v, tid);
    int excl = incl - v + d_boff[blockIdx.x];
    if (i < NN) {
        d_rowptr[i] = excl;
        d_pos[i]    = excl;
        if (i == NN - 1) d_rowptr[NN] = excl + v;
    }
}

__global__ void k_scatter(const int* __restrict__ row, const int* __restrict__ col,
                          const float* __restrict__ val) {
    int i = blockIdx.x * blockDim.x + threadIdx.x;
    int stride = gridDim.x * blockDim.x;
    for (; i < NNZ; i += stride) {
        int r = row[i];
        int p = atomicAdd(&d_pos[r], 1);
        d_edge[p] = make_int2(col[i], __float_as_int(val[i]));
    }
}

// ---- fp16 row gather helper: lane l owns 4 consecutive halves of a 64-col row
__device__ __forceinline__ float4 gather_row_h(const __half* base, int node, int l) {
    uint2 u = ((const uint2*)base)[(size_t)node * 16 + l];
    __half2 h0 = *(__half2*)&u.x;
    __half2 h1 = *(__half2*)&u.y;
    float2 f0 = __half22float2(h0);
    float2 f1 = __half22float2(h1);
    return make_float4(f0.x, f0.y, f1.x, f1.y);
}

// ---------------- layer 0: rep0 = rs^-0.5 * (sum embH[nbr] + embH[self]) * w --
// 16-lane groups, 2 rows per warp, 4 cols per lane
__global__ void k_rep0(const float* __restrict__ w) {
    int lane = threadIdx.x & 31;
    int l = lane & 15;
    int sbase = lane & 16;
    int gw = (blockIdx.x * blockDim.x + threadIdx.x) >> 4;
    if (gw >= NN) return;
    int beg = d_rowptr[gw], end = d_rowptr[gw + 1];
    int len = end - beg;
    int olen = __shfl_xor_sync(0xffffffffu, len, 16);
    int maxlen = max(len, olen);

    int self = NN + (gw >= N_USERS ? 1 : 0);
    float4 s = gather_row_h(d_embH, self, l);

    for (int r0 = 0; r0 < maxlen; r0 += 16) {
        int jj = beg + r0 + l;
        int c = 0; float m = 0.f;
        if (jj < end) { c = d_edge[jj].x; m = 1.f; }
        int kmax = min(16, maxlen - r0);
        #pragma unroll 4
        for (int k = 0; k < kmax; k++) {
            int   cc = __shfl_sync(0xffffffffu, c, sbase + k);
            float mm = __shfl_sync(0xffffffffu, m, sbase + k);
            float4 x = gather_row_h(d_embH, cc, l);
            s.x += mm * x.x; s.y += mm * x.y; s.z += mm * x.z; s.w += mm * x.w;
        }
    }
    float fv = rsqrtf((float)(len + 1));
    float4 w4 = ((const float4*)w)[l];
    s.x *= fv * w4.x; s.y *= fv * w4.y; s.z *= fv * w4.z; s.w *= fv * w4.w;

    size_t idx = (size_t)gw * 16 + l;
    ((float4*)d_accm)[idx] = s;
    __half2 h0 = __floats2half2_rn(s.x, s.y);
    __half2 h1 = __floats2half2_rn(s.z, s.w);
    ((uint2*)d_repHA)[idx] = make_uint2(*(unsigned*)&h0, *(unsigned*)&h1);
}

// ---------------- adj SpMM layer: out = A * in ; acc += out ------------------
__global__ void k_spmm(int flip) {
    const __half* in  = flip ? d_repHB : d_repHA;
    __half*       out = flip ? d_repHA : d_repHB;
    int lane = threadIdx.x & 31;
    int l = lane & 15;
    int sbase = lane & 16;
    int gw = (blockIdx.x * blockDim.x + threadIdx.x) >> 4;
    if (gw >= NN) return;
    int beg = d_rowptr[gw], end = d_rowptr[gw + 1];
    int len = end - beg;
    int olen = __shfl_xor_sync(0xffffffffu, len, 16);
    int maxlen = max(len, olen);

    float4 s = make_float4(0.f, 0.f, 0.f, 0.f);
    for (int r0 = 0; r0 < maxlen; r0 += 16) {
        int jj = beg + r0 + l;
        int c = 0; float v = 0.f;
        if (jj < end) { int2 e = d_edge[jj]; c = e.x; v = __int_as_float(e.y); }
        int kmax = min(16, maxlen - r0);
        #pragma unroll 4
        for (int k = 0; k < kmax; k++) {
            int   cc = __shfl_sync(0xffffffffu, c, sbase + k);
            float vv = __shfl_sync(0xffffffffu, v, sbase + k);
            float4 x = gather_row_h(in, cc, l);
            s.x += vv * x.x; s.y += vv * x.y; s.z += vv * x.z; s.w += vv * x.w;
        }
    }
    size_t idx = (size_t)gw * 16 + l;
    __half2 h0 = __floats2half2_rn(s.x, s.y);
    __half2 h1 = __floats2half2_rn(s.z, s.w);
    ((uint2*)out)[idx] = make_uint2(*(unsigned*)&h0, *(unsigned*)&h1);

    float4* a = (float4*)d_accm;
    float4 av = a[idx];
    av.x += s.x; av.y += s.y; av.z += s.z; av.w += s.w;
    a[idx] = av;
}

// ---------------- gather users, fold the /16 ---------------------------------
__global__ void k_gatherU(const int* __restrict__ users) {
    int t = blockIdx.x * blockDim.x + threadIdx.x;
    if (t < BATCH * EMB) {
        int b = t >> 6, c = t & 63;
        d_U[t] = d_accm[(size_t)users[b] * EMB + c] * (1.0f / 16.0f);
    }
}

// ---------------- final GEMM: out[512][150000] = U(512x64) * I(150000x64)^T --
// block tile 64u x 128i, 128 threads, thread tile 8u x 8i, FFMA2 packed math
__global__ __launch_bounds__(128) void k_gemm(float* __restrict__ out) {
    __shared__ float Us[64][64];    // [k][user] 16KB
    __shared__ float Is[64][128];   // [k][item] 32KB
    int tid = threadIdx.x;
    int tx = tid & 15;              // item group (8 items)
    int ty = tid >> 4;              // user group (8 users)
    int it0 = blockIdx.x * 128;
    int u0  = blockIdx.y * 64;

    {
        int user = tid >> 1;
        int kh = (tid & 1) * 32;
        const float4* src = (const float4*)&d_U[(u0 + user) * EMB + kh];
        #pragma unroll
        for (int j = 0; j < 8; j++) {
            float4 f = src[j];
            int k = kh + j * 4;
            Us[k + 0][user] = f.x;
            Us[k + 1][user] = f.y;
            Us[k + 2][user] = f.z;
            Us[k + 3][user] = f.w;
        }
    }
    {
        int git = it0 + tid;
        if (git < N_ITEMS) {
            const float4* src = (const float4*)&d_accm[(size_t)(N_USERS + git) * EMB];
            #pragma unroll
            for (int j = 0; j < 16; j++) {
                float4 f = src[j];
                int k = j * 4;
                Is[k + 0][tid] = f.x;
                Is[k + 1][tid] = f.y;
                Is[k + 2][tid] = f.z;
                Is[k + 3][tid] = f.w;
            }
        } else {
            #pragma unroll
            for (int k = 0; k < 64; k++) Is[k][tid] = 0.f;
        }
    }
    __syncthreads();

    unsigned long long acc[8][4];
    #pragma unroll
    for (int u = 0; u < 8; u++)
        #pragma unroll
        for (int p = 0; p < 4; p++) acc[u][p] = 0ULL;

    #pragma unroll 4
    for (int k = 0; k < 64; k++) {
        float4 a0 = *(const float4*)&Us[k][ty * 8];
        float4 a1 = *(const float4*)&Us[k][ty * 8 + 4];
        const ulonglong2* ip = (const ulonglong2*)&Is[k][tx * 8];
        ulonglong2 i01 = ip[0];
        ulonglong2 i23 = ip[1];
        unsigned long long iv[4] = {i01.x, i01.y, i23.x, i23.y};
        unsigned long long ud[8];
        DUP2(ud[0], a0.x); DUP2(ud[1], a0.y); DUP2(ud[2], a0.z); DUP2(ud[3], a0.w);
        DUP2(ud[4], a1.x); DUP2(ud[5], a1.y); DUP2(ud[6], a1.z); DUP2(ud[7], a1.w);
        #pragma unroll
        for (int u = 0; u < 8; u++)
            #pragma unroll
            for (int p = 0; p < 4; p++)
                FMA2(acc[u][p], ud[u], iv[p]);
    }

    int it = it0 + tx * 8;
    bool full = (it0 + 128 <= N_ITEMS);
    #pragma unroll
    for (int u = 0; u < 8; u++) {
        float r[8];
        #pragma unroll
        for (int p = 0; p < 4; p++) UNPK2(r[2 * p], r[2 * p + 1], acc[u][p]);
        float* orow = &out[(size_t)(u0 + ty * 8 + u) * N_ITEMS + it];
        if (full) {
            *(float4*)&orow[0] = make_float4(r[0], r[1], r[2], r[3]);
            *(float4*)&orow[4] = make_float4(r[4], r[5], r[6], r[7]);
        } else {
            #pragma unroll
            for (int j = 0; j < 8; j++)
                if (it + j < N_ITEMS) orow[j] = r[j];
        }
    }
}

// ---------------- launch -----------------------------------------------------
extern "C" void kernel_launch(void* const* d_in, const int* in_sizes, int n_in,
                              void* d_out, int out_size) {
    const int*   users = (const int*)  d_in[0];
    const float* emb   = (const float*)d_in[1];
    const float* w     = (const float*)d_in[2];
    const int*   arow  = (const int*)  d_in[3];
    const int*   acol  = (const int*)  d_in[4];
    const float* aval  = (const float*)d_in[5];
    float* out = (float*)d_out;

    k_cvt_emb<<<(NFEAT * EMB / 4 + 255) / 256, 256>>>(emb);
    k_zero<<<(NN + 255) / 256, 256>>>();
    k_hist<<<2048, 256>>>(arow);
    k_csr1<<<SCAN_B, SCAN_T>>>();
    k_csr2<<<1, 256>>>();
    k_csr3<<<SCAN_B, SCAN_T>>>();
    k_scatter<<<2048, 256>>>(arow, acol, aval);

    int blocks = (NN * 16 + 255) / 256;    // 16 lanes per row
    k_rep0<<<blocks, 256>>>(w);
    k_spmm<<<blocks, 256>>>(0);    // HA -> HB
    k_spmm<<<blocks, 256>>>(1);    // HB -> HA
    k_spmm<<<blocks, 256>>>(0);    // HA -> HB

    k_gatherU<<<(BATCH * EMB + 255) / 256, 256>>>(users);

    dim3 g((N_ITEMS + 127) / 128, BATCH / 64);
    k_gemm<<<g, 128>>>(out);
}

// round 4
// speedup vs baseline: 3.4490x; 1.3823x over previous
#include <cuda_runtime.h>
#include <cuda_bf16.h>
#include <cuda_fp16.h>

#define N_USERS 100000
#define N_ITEMS 150000
#define NN      250000
#define NFEAT   250002
#define NNZ     4000000
#define EMB     64
#define BATCH   512

#define SCAN_T  1024
#define SCAN_B  ((NN + SCAN_T - 1) / SCAN_T)   // 245

// ---------------- scratch (device globals; no runtime allocation) ------------
__device__ int    d_cnt[NN];
__device__ int    d_rowptr[NN + 1];
__device__ int    d_pos[NN];
__device__ int2   d_edge[NNZ];
__device__ int    d_bsum[SCAN_B];
__device__ int    d_boff[SCAN_B];
__device__ __half d_embH[(size_t)NFEAT * EMB];
__device__ __half d_repHA[(size_t)NN * EMB];
__device__ __half d_repHB[(size_t)NN * EMB];
__device__ float  d_accm[(size_t)NN * EMB];
__device__ __half d_Uh[BATCH * EMB];
__device__ __half d_Ih[(size_t)N_ITEMS * EMB];

// ---------------- emb -> fp16 ------------------------------------------------
__global__ void k_cvt_emb(const float* __restrict__ emb) {
    int i = blockIdx.x * blockDim.x + threadIdx.x;            // float4 index
    const int total = (NFEAT * EMB) / 4;
    if (i < total) {
        float4 f = ((const float4*)emb)[i];
        __half2 h0 = __floats2half2_rn(f.x, f.y);
        __half2 h1 = __floats2half2_rn(f.z, f.w);
        ((uint2*)d_embH)[i] = make_uint2(*(unsigned*)&h0, *(unsigned*)&h1);
    }
}

// ---------------- CSR build --------------------------------------------------
__global__ void k_hist(const int* __restrict__ row) {
    int i = blockIdx.x * blockDim.x + threadIdx.x;
    int stride = gridDim.x * blockDim.x;
    for (; i < NNZ / 4; i += stride) {
        int4 r = ((const int4*)row)[i];
        atomicAdd(&d_cnt[r.x], 1);
        atomicAdd(&d_cnt[r.y], 1);
        atomicAdd(&d_cnt[r.z], 1);
        atomicAdd(&d_cnt[r.w], 1);
    }
}

__device__ __forceinline__ int block_scan_incl(int v, int tid) {
    int lane = tid & 31, w = tid >> 5;
    int x = v;
    #pragma unroll
    for (int o = 1; o < 32; o <<= 1) {
        int y = __shfl_up_sync(0xffffffffu, x, o);
        if (lane >= o) x += y;
    }
    __shared__ int ws[32];
    if (lane == 31) ws[w] = x;
    __syncthreads();
    if (w == 0) {
        int y = ws[lane];
        #pragma unroll
        for (int o = 1; o < 32; o <<= 1) {
            int z = __shfl_up_sync(0xffffffffu, y, o);
            if (lane >= o) y += z;
        }
        ws[lane] = y;
    }
    __syncthreads();
    return x + (w > 0 ? ws[w - 1] : 0);
}

__global__ void k_csr1() {
    int tid = threadIdx.x;
    int i = blockIdx.x * SCAN_T + tid;
    int v = (i < NN) ? d_cnt[i] : 0;
    int incl = block_scan_incl(v, tid);
    if (tid == SCAN_T - 1) d_bsum[blockIdx.x] = incl;
}

__global__ void k_csr2() {
    int tid = threadIdx.x;
    int v = (tid < SCAN_B) ? d_bsum[tid] : 0;
    int lane = tid & 31, w = tid >> 5;
    int x = v;
    #pragma unroll
    for (int o = 1; o < 32; o <<= 1) {
        int y = __shfl_up_sync(0xffffffffu, x, o);
        if (lane >= o) x += y;
    }
    __shared__ int ws[8];
    if (lane == 31) ws[w] = x;
    __syncthreads();
    int off = 0;
    for (int j = 0; j < w; j++) off += ws[j];
    if (tid < SCAN_B) d_boff[tid] = x + off - v;
}

__global__ void k_csr3() {
    int tid = threadIdx.x;
    int i = blockIdx.x * SCAN_T + tid;
    int v = (i < NN) ? d_cnt[i] : 0;
    int incl = block_scan_incl(v, tid);
    int excl = incl - v + d_boff[blockIdx.x];
    if (i < NN) {
        d_rowptr[i] = excl;
        d_pos[i]    = excl;
        if (i == NN - 1) d_rowptr[NN] = excl + v;
    }
}

__global__ void k_scatter(const int* __restrict__ row, const int* __restrict__ col,
                          const float* __restrict__ val) {
    int i = blockIdx.x * blockDim.x + threadIdx.x;
    int stride = gridDim.x * blockDim.x;
    for (; i < NNZ; i += stride) {
        int r = row[i];
        int p = atomicAdd(&d_pos[r], 1);
        d_edge[p] = make_int2(col[i], __float_as_int(val[i]));
    }
}

// ---- fp16 row gather helper: lane l owns 4 consecutive halves of a 64-col row
__device__ __forceinline__ float4 gather_row_h(const __half* base, int node, int l) {
    uint2 u = ((const uint2*)base)[(size_t)node * 16 + l];
    __half2 h0 = *(__half2*)&u.x;
    __half2 h1 = *(__half2*)&u.y;
    float2 f0 = __half22float2(h0);
    float2 f1 = __half22float2(h1);
    return make_float4(f0.x, f0.y, f1.x, f1.y);
}

// ---------------- layer 0: rep0 = rs^-0.5 * (sum embH[nbr] + embH[self]) * w --
__global__ void k_rep0(const float* __restrict__ w) {
    int lane = threadIdx.x & 31;
    int l = lane & 15;
    int sbase = lane & 16;
    int gw = (blockIdx.x * blockDim.x + threadIdx.x) >> 4;
    if (gw >= NN) return;
    int beg = d_rowptr[gw], end = d_rowptr[gw + 1];
    int len = end - beg;
    int olen = __shfl_xor_sync(0xffffffffu, len, 16);
    int maxlen = max(len, olen);

    int self = NN + (gw >= N_USERS ? 1 : 0);
    float4 s = gather_row_h(d_embH, self, l);

    for (int r0 = 0; r0 < maxlen; r0 += 16) {
        int jj = beg + r0 + l;
        int c = 0; float m = 0.f;
        if (jj < end) { c = d_edge[jj].x; m = 1.f; }
        int kmax = min(16, maxlen - r0);
        #pragma unroll 4
        for (int k = 0; k < kmax; k++) {
            int   cc = __shfl_sync(0xffffffffu, c, sbase + k);
            float mm = __shfl_sync(0xffffffffu, m, sbase + k);
            float4 x = gather_row_h(d_embH, cc, l);
            s.x += mm * x.x; s.y += mm * x.y; s.z += mm * x.z; s.w += mm * x.w;
        }
    }
    float fv = rsqrtf((float)(len + 1));
    float4 w4 = ((const float4*)w)[l];
    s.x *= fv * w4.x; s.y *= fv * w4.y; s.z *= fv * w4.z; s.w *= fv * w4.w;

    size_t idx = (size_t)gw * 16 + l;
    ((float4*)d_accm)[idx] = s;
    __half2 h0 = __floats2half2_rn(s.x, s.y);
    __half2 h1 = __floats2half2_rn(s.z, s.w);
    ((uint2*)d_repHA)[idx] = make_uint2(*(unsigned*)&h0, *(unsigned*)&h1);
}

// ---------------- adj SpMM layer: out = A * in ; acc += out ------------------
// last=1: also emit fp16 item matrix rows (final accm for nodes >= N_USERS)
__global__ void k_spmm(int flip, int last) {
    const __half* in  = flip ? d_repHB : d_repHA;
    __half*       out = flip ? d_repHA : d_repHB;
    int lane = threadIdx.x & 31;
    int l = lane & 15;
    int sbase = lane & 16;
    int gw = (blockIdx.x * blockDim.x + threadIdx.x) >> 4;
    if (gw >= NN) return;
    int beg = d_rowptr[gw], end = d_rowptr[gw + 1];
    int len = end - beg;
    int olen = __shfl_xor_sync(0xffffffffu, len, 16);
    int maxlen = max(len, olen);

    float4 s = make_float4(0.f, 0.f, 0.f, 0.f);
    for (int r0 = 0; r0 < maxlen; r0 += 16) {
        int jj = beg + r0 + l;
        int c = 0; float v = 0.f;
        if (jj < end) { int2 e = d_edge[jj]; c = e.x; v = __int_as_float(e.y); }
        int kmax = min(16, maxlen - r0);
        #pragma unroll 4
        for (int k = 0; k < kmax; k++) {
            int   cc = __shfl_sync(0xffffffffu, c, sbase + k);
            float vv = __shfl_sync(0xffffffffu, v, sbase + k);
            float4 x = gather_row_h(in, cc, l);
            s.x += vv * x.x; s.y += vv * x.y; s.z += vv * x.z; s.w += vv * x.w;
        }
    }
    size_t idx = (size_t)gw * 16 + l;
    __half2 h0 = __floats2half2_rn(s.x, s.y);
    __half2 h1 = __floats2half2_rn(s.z, s.w);
    ((uint2*)out)[idx] = make_uint2(*(unsigned*)&h0, *(unsigned*)&h1);

    float4* a = (float4*)d_accm;
    float4 av = a[idx];
    av.x += s.x; av.y += s.y; av.z += s.z; av.w += s.w;
    a[idx] = av;

    if (last && gw >= N_USERS) {
        __half2 g0 = __floats2half2_rn(av.x, av.y);
        __half2 g1 = __floats2half2_rn(av.z, av.w);
        ((uint2*)d_Ih)[(size_t)(gw - N_USERS) * 16 + l] =
            make_uint2(*(unsigned*)&g0, *(unsigned*)&g1);
    }
}

// ---------------- gather users -> fp16, fold the /16 --------------------------
__global__ void k_gatherU(const int* __restrict__ users) {
    int t = blockIdx.x * blockDim.x + threadIdx.x;
    if (t < BATCH * EMB / 2) {
        int b = t >> 5, c = (t & 31) * 2;
        const float* src = &d_accm[(size_t)users[b] * EMB + c];
        __half2 h = __floats2half2_rn(src[0] * (1.0f / 16.0f), src[1] * (1.0f / 16.0f));
        ((__half2*)d_Uh)[t] = h;
    }
}

// ---------------- tensor-core GEMM: out[512][150000] = Uh * Ih^T --------------
// block: 256 thr (8 warps), tile 64 users x 128 items, K=64
// warp: 16m x 64n (warp_m = wid&3, warp_n = wid>>2)
__device__ __forceinline__ unsigned smem_u32(const void* p) {
    return (unsigned)__cvta_generic_to_shared(p);
}

__global__ __launch_bounds__(256) void k_gemm_tc(float* __restrict__ out) {
    __shared__ __half Us[64][72];    // [m][k], pad 72 halves = 144B stride
    __shared__ __half Is[128][72];   // [n][k]
    int tid = threadIdx.x;
    int wid = tid >> 5, lane = tid & 31;
    int it0 = blockIdx.x * 128;
    int u0  = blockIdx.y * 64;

    // load U tile: 64 rows x 64 halves = 512 x uint4
    for (int i = tid; i < 64 * 8; i += 256) {
        int r = i >> 3, c = i & 7;
        *(uint4*)&Us[r][c * 8] = ((const uint4*)d_Uh)[(u0 + r) * 8 + c];
    }
    // load I tile: 128 rows x 64 halves, zero-pad past N_ITEMS
    for (int i = tid; i < 128 * 8; i += 256) {
        int r = i >> 3, c = i & 7;
        int git = it0 + r;
        uint4 v = make_uint4(0u, 0u, 0u, 0u);
        if (git < N_ITEMS) v = ((const uint4*)d_Ih)[(size_t)git * 8 + c];
        *(uint4*)&Is[r][c * 8] = v;
    }
    __syncthreads();

    int wm = (wid & 3) * 16;
    int wn = (wid >> 2) * 64;

    float acc[8][4];
    #pragma unroll
    for (int n = 0; n < 8; n++)
        #pragma unroll
        for (int j = 0; j < 4; j++) acc[n][j] = 0.f;

    #pragma unroll
    for (int ks = 0; ks < 4; ks++) {
        int k0 = ks * 16;
        // A fragment (m16k16) via ldmatrix.x4
        unsigned a0, a1, a2, a3;
        {
            const __half* ap = (lane < 16) ? &Us[wm + lane][k0]
                                           : &Us[wm + lane - 16][k0 + 8];
            unsigned addr = smem_u32(ap);
            asm volatile("ldmatrix.sync.aligned.m8n8.x4.shared.b16 {%0,%1,%2,%3}, [%4];"
                         : "=r"(a0), "=r"(a1), "=r"(a2), "=r"(a3) : "r"(addr));
        }
        #pragma unroll
        for (int nt = 0; nt < 8; nt += 2) {
            // two B fragments (k16n8 each) via one ldmatrix.x4 (no trans):
            // lanes 0-7:   I[wn+nt*8+l][k0]        -> b0 (frag nt,  k0..7)
            // lanes 8-15:  I[wn+nt*8+l-8][k0+8]    -> b1 (frag nt,  k8..15)
            // lanes 16-23: I[wn+nt*8+8+l-16][k0]   -> b2 (frag nt+1,k0..7)
            // lanes 24-31: I[wn+nt*8+8+l-24][k0+8] -> b3 (frag nt+1,k8..15)
            unsigned b0, b1, b2, b3;
            int sub = lane >> 3;                  // 0..3
            int rr  = wn + nt * 8 + (lane & 7) + ((sub >> 1) * 8);
            int kk  = k0 + (sub & 1) * 8;
            unsigned addr = smem_u32(&Is[rr][kk]);
            asm volatile("ldmatrix.sync.aligned.m8n8.x4.shared.b16 {%0,%1,%2,%3}, [%4];"
                         : "=r"(b0), "=r"(b1), "=r"(b2), "=r"(b3) : "r"(addr));
            asm volatile("mma.sync.aligned.m16n8k16.row.col.f32.f16.f16.f32 "
                         "{%0,%1,%2,%3}, {%4,%5,%6,%7}, {%8,%9}, {%0,%1,%2,%3};"
                         : "+f"(acc[nt][0]), "+f"(acc[nt][1]), "+f"(acc[nt][2]), "+f"(acc[nt][3])
                         : "r"(a0), "r"(a1), "r"(a2), "r"(a3), "r"(b0), "r"(b1));
            asm volatile("mma.sync.aligned.m16n8k16.row.col.f32.f16.f16.f32 "
                         "{%0,%1,%2,%3}, {%4,%5,%6,%7}, {%8,%9}, {%0,%1,%2,%3};"
                         : "+f"(acc[nt+1][0]), "+f"(acc[nt+1][1]), "+f"(acc[nt+1][2]), "+f"(acc[nt+1][3])
                         : "r"(a0), "r"(a1), "r"(a2), "r"(a3), "r"(b2), "r"(b3));
        }
    }

    // store: frag (nt): rows m0=lane/4, m0+8 ; cols nt*8 + (lane%4)*2 (+1)
    int m0 = u0 + wm + (lane >> 2);
    int cbase = it0 + wn + (lane & 3) * 2;
    #pragma unroll
    for (int nt = 0; nt < 8; nt++) {
        int col = cbase + nt * 8;
        if (col < N_ITEMS) {   // N_ITEMS even, col even -> float2 safe
            *(float2*)&out[(size_t)m0 * N_ITEMS + col]       = make_float2(acc[nt][0], acc[nt][1]);
            *(float2*)&out[(size_t)(m0 + 8) * N_ITEMS + col] = make_float2(acc[nt][2], acc[nt][3]);
        }
    }
}

// ---------------- launch -----------------------------------------------------
extern "C" void kernel_launch(void* const* d_in, const int* in_sizes, int n_in,
                              void* d_out, int out_size) {
    const int*   users = (const int*)  d_in[0];
    const float* emb   = (const float*)d_in[1];
    const float* w     = (const float*)d_in[2];
    const int*   arow  = (const int*)  d_in[3];
    const int*   acol  = (const int*)  d_in[4];
    const float* aval  = (const float*)d_in[5];
    float* out = (float*)d_out;

    void* cntp = nullptr;
    cudaGetSymbolAddress(&cntp, d_cnt);
    cudaMemsetAsync(cntp, 0, NN * sizeof(int));

    k_cvt_emb<<<(NFEAT * EMB / 4 + 255) / 256, 256>>>(emb);
    k_hist<<<2048, 256>>>(arow);
    k_csr1<<<SCAN_B, SCAN_T>>>();
    k_csr2<<<1, 256>>>();
    k_csr3<<<SCAN_B, SCAN_T>>>();
    k_scatter<<<2048, 256>>>(arow, acol, aval);

    int blocks = (NN * 16 + 255) / 256;    // 16 lanes per row
    k_rep0<<<blocks, 256>>>(w);
    k_spmm<<<blocks, 256>>>(0, 0);    // HA -> HB
    k_spmm<<<blocks, 256>>>(1, 0);    // HB -> HA
    k_spmm<<<blocks, 256>>>(0, 1);    // HA -> HB, emit d_Ih

    k_gatherU<<<(BATCH * EMB / 2 + 255) / 256, 256>>>(users);

    dim3 g((N_ITEMS + 127) / 128, BATCH / 64);
    k_gemm_tc<<<g, 256>>>(out);
}